// round 16
// baseline (speedup 1.0000x reference)
#include <cuda_runtime.h>
#include <cuda_fp16.h>
#include <math.h>
#include <cstdint>

// Problem constants (fixed by the reference)
#define GM 50000        // nodes
#define GK 3703         // input dim
#define GKP 3712        // padded K (multiple of 32)
#define GN 256          // hidden dim
#define GE 400000       // edges
#define GO 6            // output classes

#define BK 32           // K per chunk
#define NCH (GKP / BK)  // 116

#define A32ROWB 144     // fp32 A smem row stride (128B data + 16 pad; /16 = 9 odd)
#define A32STAGE (128 * A32ROWB)      // 18432
#define BROWB 80        // fp16 B smem row stride (64B data + 16 pad)
#define BSTAGE (128 * BROWB)          // 10240
#define CSTAGE (A32STAGE + BSTAGE)    // 28672
#define NSTAGE 3
#define AH_OFF (NSTAGE * CSTAGE)      // 86016  (fp16 A double buffer)
#define AHROWB 80
#define AHBUF (128 * AHROWB)          // 10240
#define SMEM_TOTAL (AH_OFF + 2 * AHBUF)   // 106496

// ---------------- scratch (static device memory; no allocation) ----------------
__device__ __align__(16) float  g_support1[(size_t)GM * GN];  // X @ W1    (51.2 MB)
__device__ __align__(16) float  g_support2[(size_t)GM * GO];  // h1 @ W2   (1.2 MB)
__device__ __align__(16) __half g_W1th[(size_t)GN * GKP];     // fp16 W1^T, padded (1.9 MB)
__device__ int   g_deg[GM];
__device__ int   g_cur[GM];
__device__ int   g_off[GM + 1];
__device__ int   g_ssrc[GE];
__device__ float g_sw[GE];

// ---------------- ptx helpers ----------------
__device__ __forceinline__ uint32_t smem_u32(const void* p) {
    uint32_t a;
    asm("{ .reg .u64 t; cvta.to.shared.u64 t, %1; cvt.u32.u64 %0, t; }" : "=r"(a) : "l"(p));
    return a;
}

__device__ __forceinline__ void cp_async16(uint32_t dst, const void* src) {
    asm volatile("cp.async.cg.shared.global [%0], [%1], 16;" :: "r"(dst), "l"(src));
}
// 4-byte cp.async with zero-fill (src-size register): alignment-safe for fp32 X rows
__device__ __forceinline__ void cp_async4z(uint32_t dst, const void* src, int sz) {
    asm volatile("cp.async.ca.shared.global [%0], [%1], 4, %2;"
                 :: "r"(dst), "l"(src), "r"(sz));
}
#define CP_COMMIT() asm volatile("cp.async.commit_group;" ::: "memory")
#define CP_WAIT1()  asm volatile("cp.async.wait_group 1;" ::: "memory")
#define CP_WAIT2()  asm volatile("cp.async.wait_group 2;" ::: "memory")

__device__ __forceinline__ void ldsm_x4(uint32_t* r, uint32_t addr) {
    asm volatile("ldmatrix.sync.aligned.m8n8.x4.shared.b16 {%0,%1,%2,%3}, [%4];"
                 : "=r"(r[0]), "=r"(r[1]), "=r"(r[2]), "=r"(r[3]) : "r"(addr));
}

__device__ __forceinline__ void mma_f16(float* c, const uint32_t* a, const uint32_t* b) {
    asm volatile(
        "mma.sync.aligned.m16n8k16.row.col.f32.f16.f16.f32 "
        "{%0,%1,%2,%3}, {%4,%5,%6,%7}, {%8,%9}, {%0,%1,%2,%3};"
        : "+f"(c[0]), "+f"(c[1]), "+f"(c[2]), "+f"(c[3])
        : "r"(a[0]), "r"(a[1]), "r"(a[2]), "r"(a[3]),
          "r"(b[0]), "r"(b[1]));
}

// ---------------- edge preprocessing ----------------
__global__ void zero_kernel() {
    int i = blockIdx.x * blockDim.x + threadIdx.x;
    if (i < GM) { g_deg[i] = 0; g_cur[i] = 0; }
}

__global__ void hist_kernel(const int* __restrict__ dst) {
    int e = blockIdx.x * blockDim.x + threadIdx.x;
    if (e < GE) atomicAdd(&g_deg[dst[e]], 1);
}

__global__ void scan_kernel() {
    __shared__ int sh[1024];
    const int t = threadIdx.x;
    const int CH = 49;
    int base = t * CH;
    int s = 0;
    #pragma unroll 7
    for (int i = 0; i < CH; i++) {
        int idx = base + i;
        if (idx < GM) s += g_deg[idx];
    }
    sh[t] = s;
    __syncthreads();
    for (int off = 1; off < 1024; off <<= 1) {
        int v = 0;
        if (t >= off) v = sh[t - off];
        __syncthreads();
        if (t >= off) sh[t] += v;
        __syncthreads();
    }
    int run = (t == 0) ? 0 : sh[t - 1];
    for (int i = 0; i < CH; i++) {
        int idx = base + i;
        if (idx < GM) { g_off[idx] = run; run += g_deg[idx]; }
    }
    if (t == 1023) g_off[GM] = sh[1023];
}

__global__ void bucket_kernel(const int* __restrict__ src,
                              const int* __restrict__ dst,
                              const float* __restrict__ w) {
    int e = blockIdx.x * blockDim.x + threadIdx.x;
    if (e < GE) {
        int d = dst[e];
        int r = atomicAdd(&g_cur[d], 1);
        int p = g_off[d] + r;
        g_ssrc[p] = src[e];
        g_sw[p]   = w[e];
    }
}

// ---------------- W1[k][n] -> g_W1th[n][kk] fp16, zero-padded to GKP ----------------
__global__ void wconv_kernel(const float* __restrict__ W1) {
    __shared__ float tile[32][33];
    const int k0 = blockIdx.x * 32;     // 116 blocks
    const int n0 = blockIdx.y * 32;     // 8 blocks
    const int tx = threadIdx.x, ty = threadIdx.y;   // 32 x 8
    #pragma unroll
    for (int i = 0; i < 4; i++) {
        int k = k0 + ty + i * 8;
        tile[ty + i * 8][tx] = (k < GK) ? W1[(size_t)k * GN + n0 + tx] : 0.f;
    }
    __syncthreads();
    #pragma unroll
    for (int i = 0; i < 4; i++) {
        int n = n0 + ty + i * 8;
        g_W1th[(size_t)n * GKP + k0 + tx] = __float2half(tile[tx][ty + i * 8]);
    }
}

// ---------------- GEMM1: support1 = fp16(X) @ fp16(W1), fp32 accumulate ----------------
// fp32 X staged via cp.async.ca 4B into a 3-stage smem ring; converted to a
// fp16 double buffer one chunk ahead of compute (transient registers only).
// CTA tile 128x128, 8 warps (2Mx4N), warp tile 64x32, m16n8k16 fp16 MMA.

__device__ __forceinline__ void issue_chunk(const float* __restrict__ x,
                                            int m0, int n0, int kb,
                                            uint32_t stageBase, int tid) {
    const int k0 = kb * BK;
    const int col = tid & 31;           // fixed per thread
    const int wrow = tid >> 5;          // 0..7
    const int vsz = (k0 + col < GK) ? 4 : 0;   // zero-fill k-tail (values x0 anyway)
    // A: fp32, 16 x 4B per thread (rows wrow, wrow+8, ..., wrow+120)
    #pragma unroll
    for (int i = 0; i < 16; i++) {
        int row = i * 8 + wrow;
        int gm = m0 + row; if (gm >= GM) gm = GM - 1;
        cp_async4z(stageBase + row * A32ROWB + col * 4,
                   x + (size_t)gm * GK + k0 + col, vsz);
    }
    // B: fp16, 2 x 16B per thread
    const uint32_t bBase = stageBase + A32STAGE;
    #pragma unroll
    for (int j = 0; j < 2; j++) {
        int c = tid * 2 + j;
        int n = c >> 2, q = c & 3;
        cp_async16(bBase + n * BROWB + q * 16,
                   g_W1th + (size_t)(n0 + n) * GKP + k0 + q * 8);
    }
}

// convert fp32 A stage -> fp16 A buffer (transient regs only)
__device__ __forceinline__ void convertA(uint32_t a32, uint32_t ah, int tid) {
    const int row = tid >> 1;
    const int h   = tid & 1;
    const uint32_t s = a32 + row * A32ROWB + h * 64;
    const uint32_t d = ah  + row * AHROWB  + h * 32;
    float f[16];
    #pragma unroll
    for (int j = 0; j < 4; j++)
        asm volatile("ld.shared.v4.f32 {%0,%1,%2,%3}, [%4];"
                     : "=f"(f[4*j]), "=f"(f[4*j+1]), "=f"(f[4*j+2]), "=f"(f[4*j+3])
                     : "r"(s + j * 16));
    uint32_t hh[8];
    #pragma unroll
    for (int j = 0; j < 8; j++) {
        __half2 hv = __floats2half2_rn(f[2*j], f[2*j+1]);
        hh[j] = *reinterpret_cast<uint32_t*>(&hv);
    }
    asm volatile("st.shared.v4.b32 [%0], {%1,%2,%3,%4};"
                 :: "r"(d), "r"(hh[0]), "r"(hh[1]), "r"(hh[2]), "r"(hh[3]));
    asm volatile("st.shared.v4.b32 [%0], {%1,%2,%3,%4};"
                 :: "r"(d + 16), "r"(hh[4]), "r"(hh[5]), "r"(hh[6]), "r"(hh[7]));
}

__global__ __launch_bounds__(256, 2)
void gemm1_kernel(const float* __restrict__ x) {
    extern __shared__ char smem[];
    const uint32_t sbase = smem_u32(smem);
    const int tid  = threadIdx.x;
    const int wid  = tid >> 5;
    const int lane = tid & 31;
    const int wr   = wid & 1;          // warp M (0..1) -> 64 rows
    const int wc   = wid >> 1;         // warp N (0..3) -> 32 cols
    const int m0   = blockIdx.y * 128;
    const int n0   = blockIdx.x * 128;

    // ldmatrix lane offsets
    const uint32_t aOff = (uint32_t)((wr * 64 + (lane & 15)) * AHROWB + ((lane >> 4) * 8) * 2);
    const uint32_t bOffRel =
        (uint32_t)((wc * 32 + ((lane >> 4) << 3) + (lane & 7)) * BROWB + (((lane >> 3) & 1) * 8) * 2);

    float acc[4][4][4];
    #pragma unroll
    for (int a = 0; a < 4; a++)
        #pragma unroll
        for (int b = 0; b < 4; b++)
            #pragma unroll
            for (int i = 0; i < 4; i++) acc[a][b][i] = 0.f;

    // prologue: chunks 0,1,2 in flight; convert chunk 0
    issue_chunk(x, m0, n0, 0, sbase + 0 * CSTAGE, tid); CP_COMMIT();
    issue_chunk(x, m0, n0, 1, sbase + 1 * CSTAGE, tid); CP_COMMIT();
    issue_chunk(x, m0, n0, 2, sbase + 2 * CSTAGE, tid); CP_COMMIT();
    CP_WAIT2();                 // chunk 0 resident
    __syncthreads();
    convertA(sbase + 0 * CSTAGE, sbase + AH_OFF + 0 * AHBUF, tid);

    int stage = 0;   // stage of chunk kb
    for (int kb = 0; kb < NCH; kb++) {
        // groups committed so far = 3 + kb (one per loop iter, empty at tail);
        // newest 1 = chunk kb+2 -> wait_group 1 guarantees chunk kb+1 resident.
        CP_WAIT1();
        __syncthreads();   // cp.async data visible to all; also orders prologue/prev convert

        // convert chunk kb+1 (reads A32 stage (kb+1)%3, writes Ah parity (kb+1)&1)
        const int nstage = (stage + 1 == NSTAGE) ? 0 : stage + 1;
        if (kb + 1 < NCH)
            convertA(sbase + nstage * CSTAGE, sbase + AH_OFF + ((kb + 1) & 1) * AHBUF, tid);

        // compute chunk kb from Ah(kb&1) and B stage kb%3
        const uint32_t aSb = sbase + AH_OFF + (kb & 1) * AHBUF;
        const uint32_t bSb = sbase + stage * CSTAGE + A32STAGE;
        #pragma unroll
        for (int ks = 0; ks < 2; ks++) {  // two k16 steps; +32B per step
            uint32_t af[4][4];
            #pragma unroll
            for (int mi = 0; mi < 4; mi++)
                ldsm_x4(af[mi], aSb + aOff + mi * (16 * AHROWB) + ks * 32);
            uint32_t bf[2][4];
            #pragma unroll
            for (int njp = 0; njp < 2; njp++)
                ldsm_x4(bf[njp], bSb + bOffRel + njp * (16 * BROWB) + ks * 32);
            #pragma unroll
            for (int mi = 0; mi < 4; mi++) {
                #pragma unroll
                for (int nj = 0; nj < 4; nj++) {
                    const uint32_t* bp = &bf[nj >> 1][(nj & 1) * 2];
                    mma_f16(acc[mi][nj], af[mi], bp);
                }
            }
        }

        __syncthreads();   // all warps done with stage kb%3 (B) and its A32 (converted last iter)

        // refill freed stage with chunk kb+3
        if (kb + 3 < NCH)
            issue_chunk(x, m0, n0, kb + 3, sbase + stage * CSTAGE, tid);
        CP_COMMIT();       // one group per iteration (empty at tail)

        stage = nstage;
    }

    // epilogue: acc -> g_support1
    const int rbase = m0 + wr * 64 + (lane >> 2);
    const int cbase = n0 + wc * 32 + (lane & 3) * 2;
    #pragma unroll
    for (int mi = 0; mi < 4; mi++) {
        const int r_lo = rbase + mi * 16;
        const int r_hi = r_lo + 8;
        #pragma unroll
        for (int nj = 0; nj < 4; nj++) {
            const int col = cbase + nj * 8;
            if (r_lo < GM) {
                float2 v; v.x = acc[mi][nj][0]; v.y = acc[mi][nj][1];
                *reinterpret_cast<float2*>(&g_support1[(size_t)r_lo * GN + col]) = v;
            }
            if (r_hi < GM) {
                float2 v; v.x = acc[mi][nj][2]; v.y = acc[mi][nj][3];
                *reinterpret_cast<float2*>(&g_support1[(size_t)r_hi * GN + col]) = v;
            }
        }
    }
}

// ---------------- layer-1 aggregation fused with +b1, leaky_relu, @W2 ----------------
__global__ __launch_bounds__(256)
void agg1_kernel(const float* __restrict__ b1, const float* __restrict__ W2) {
    __shared__ float sW2[GN * GO];
    __shared__ float sb1[GN];
    const int t = threadIdx.x;
    for (int i = t; i < GN * GO; i += 256) sW2[i] = W2[i];
    if (t < GN) sb1[t] = b1[t];
    __syncthreads();

    const int lane = t & 31;
    const int sub  = t >> 5;
    const int v    = blockIdx.x * 8 + sub;

    float4 a0 = make_float4(0.f, 0.f, 0.f, 0.f);
    float4 a1 = make_float4(0.f, 0.f, 0.f, 0.f);
    const int beg = g_off[v], end = g_off[v + 1];
    for (int e = beg; e < end; e++) {
        int s = g_ssrc[e];
        float w = g_sw[e];
        const float4* row = reinterpret_cast<const float4*>(g_support1 + (size_t)s * GN);
        float4 p0 = row[lane * 2];
        float4 p1 = row[lane * 2 + 1];
        a0.x += p0.x * w; a0.y += p0.y * w; a0.z += p0.z * w; a0.w += p0.w * w;
        a1.x += p1.x * w; a1.y += p1.y * w; a1.z += p1.z * w; a1.w += p1.w * w;
    }

    const int cb = lane * 8;
    float h[8];
    h[0] = a0.x + sb1[cb + 0]; h[1] = a0.y + sb1[cb + 1];
    h[2] = a0.z + sb1[cb + 2]; h[3] = a0.w + sb1[cb + 3];
    h[4] = a1.x + sb1[cb + 4]; h[5] = a1.y + sb1[cb + 5];
    h[6] = a1.z + sb1[cb + 6]; h[7] = a1.w + sb1[cb + 7];
    #pragma unroll
    for (int i = 0; i < 8; i++) h[i] = (h[i] > 0.f) ? h[i] : 0.01f * h[i];

    float p[GO];
    #pragma unroll
    for (int j = 0; j < GO; j++) p[j] = 0.f;
    #pragma unroll
    for (int i = 0; i < 8; i++) {
        const float* wr2 = &sW2[(cb + i) * GO];
        #pragma unroll
        for (int j = 0; j < GO; j++) p[j] += h[i] * wr2[j];
    }
    #pragma unroll
    for (int j = 0; j < GO; j++)
        #pragma unroll
        for (int o = 16; o > 0; o >>= 1)
            p[j] += __shfl_xor_sync(0xffffffffu, p[j], o);

    if (lane < GO) g_support2[(size_t)v * GO + lane] = p[lane];
}

// ---------------- layer-2 aggregation + b2 + log_softmax ----------------
__global__ void agg2_kernel(const float* __restrict__ b2, float* __restrict__ out) {
    int v = blockIdx.x * blockDim.x + threadIdx.x;
    if (v >= GM) return;
    float a[GO];
    #pragma unroll
    for (int j = 0; j < GO; j++) a[j] = 0.f;
    const int beg = g_off[v], end = g_off[v + 1];
    for (int e = beg; e < end; e++) {
        int s = g_ssrc[e];
        float w = g_sw[e];
        const float* r = g_support2 + (size_t)s * GO;
        #pragma unroll
        for (int j = 0; j < GO; j++) a[j] += __ldg(r + j) * w;
    }
    float l[GO];
    #pragma unroll
    for (int j = 0; j < GO; j++) l[j] = a[j] + b2[j];
    float m = l[0];
    #pragma unroll
    for (int j = 1; j < GO; j++) m = fmaxf(m, l[j]);
    float sum = 0.f;
    #pragma unroll
    for (int j = 0; j < GO; j++) sum += expf(l[j] - m);
    float ls = logf(sum);
    #pragma unroll
    for (int j = 0; j < GO; j++) out[(size_t)v * GO + j] = l[j] - m - ls;
}

// ---------------- launch ----------------
extern "C" void kernel_launch(void* const* d_in, const int* in_sizes, int n_in,
                              void* d_out, int out_size) {
    const float* x    = (const float*)d_in[0];
    const int*   esrc = (const int*)  d_in[1];
    const int*   edst = (const int*)  d_in[2];
    const float* ew   = (const float*)d_in[3];
    const float* W1   = (const float*)d_in[4];
    const float* b1   = (const float*)d_in[5];
    const float* W2   = (const float*)d_in[6];
    const float* b2   = (const float*)d_in[7];
    float* out = (float*)d_out;

    // edge preprocessing (counting sort by dst)
    zero_kernel  <<<(GM + 255) / 256, 256>>>();
    hist_kernel  <<<(GE + 255) / 256, 256>>>(edst);
    scan_kernel  <<<1, 1024>>>();
    bucket_kernel<<<(GE + 255) / 256, 256>>>(esrc, edst, ew);

    // W1 -> fp16 transposed/padded (B operand)
    wconv_kernel<<<dim3(GKP / 32, GN / 32), dim3(32, 8)>>>(W1);

    // dense transform: fp16 tensor-core GEMM with in-smem fp32->fp16 A conversion
    cudaFuncSetAttribute(gemm1_kernel,
                         cudaFuncAttributeMaxDynamicSharedMemorySize, SMEM_TOTAL);
    gemm1_kernel<<<dim3(2, (GM + 127) / 128), 256, SMEM_TOTAL>>>(x);

    // sparse agg 1 (+b1, leaky_relu, @W2 fused)
    agg1_kernel<<<GM / 8, 256>>>(b1, W2);

    // sparse agg 2 (+b2, log_softmax)
    agg2_kernel<<<(GM + 127) / 128, 128>>>(b2, out);
}